// round 2
// baseline (speedup 1.0000x reference)
#include <cuda_runtime.h>
#include <cuda_bf16.h>
#include <math.h>

// Problem constants (fixed shapes from setup_inputs)
#define BB 8
#define NN (512*512)      // points per batch
#define DD 32             // embedding dim == warp size
#define KK 64             // instances
#define PUSH_MARGIN 0.25f

// Kernel-1 tiling
#define BLOCKS_PER_BATCH 128
#define THREADS1 128
#define WARPS1 4
#define PPB (NN / BLOCKS_PER_BATCH)   // 2048 points per block
#define PPW (PPB / WARPS1)            // 512 points per warp
#define UNROLL 16

// Scratch (device globals: no allocation allowed)
__device__ float g_sums[BB * KK * DD];
__device__ float g_cnt[BB * KK];

// ---------------------------------------------------------------------------
// Kernel 0: zero scratch + output (output is poisoned before each timing run)
// ---------------------------------------------------------------------------
__global__ void zero_kernel(float* __restrict__ out) {
    int i = blockIdx.x * blockDim.x + threadIdx.x;
    if (i < BB * KK * DD) g_sums[i] = 0.0f;
    if (i < BB * KK)      g_cnt[i]  = 0.0f;
    if (i == 0)           out[0]    = 0.0f;
}

// ---------------------------------------------------------------------------
// Kernel 1: segment sum (per-batch, per-label centroid sums + counts)
//
// Each warp owns a private [K][32] accumulator in shared memory.
// Warp processes one point per step: lane d loads emb[p][d] (coalesced 128B),
// label is a broadcast load, lane d accumulates acc[l*32 + d] += v.
// Distinct address AND distinct bank per lane -> no conflicts, no atomics.
// Counts: one shared atomicAdd per point, spread across 16 lanes per group.
// ---------------------------------------------------------------------------
__global__ __launch_bounds__(THREADS1)
void seg_reduce_kernel(const float* __restrict__ emb, const int* __restrict__ lab) {
    __shared__ float sacc[WARPS1][KK * DD];   // 32 KB
    __shared__ float scnt[WARPS1][KK];        // 1 KB

    const int tid  = threadIdx.x;
    const int w    = tid >> 5;
    const int lane = tid & 31;
    const int b    = blockIdx.y;

    // zero per-warp accumulators
    for (int i = tid; i < WARPS1 * KK * DD; i += THREADS1)
        ((float*)sacc)[i] = 0.0f;
    for (int i = tid; i < WARPS1 * KK; i += THREADS1)
        ((float*)scnt)[i] = 0.0f;
    __syncthreads();

    const int p0 = blockIdx.x * PPB + w * PPW;
    const float* __restrict__ eb = emb + (size_t)b * NN * DD;
    const int*   __restrict__ lb = lab + (size_t)b * NN;
    float* __restrict__ acc = sacc[w];
    float* __restrict__ cnt = scnt[w];

    for (int p = p0; p < p0 + PPW; p += UNROLL) {
        float v[UNROLL];
        int   l[UNROLL];
#pragma unroll
        for (int j = 0; j < UNROLL; j++) {
            v[j] = eb[(size_t)(p + j) * DD + lane];  // coalesced 128B per point
            l[j] = lb[p + j];                         // broadcast (1 sector)
        }
        // counts: 16 lanes each count one point of this group
        if (lane < UNROLL)
            atomicAdd(&cnt[lb[p + lane]], 1.0f);
#pragma unroll
        for (int j = 0; j < UNROLL; j++) {
            acc[l[j] * DD + lane] += v[j];            // bank == lane: conflict-free
        }
    }
    __syncthreads();

    // Flush: combine the 4 warp accumulators, atomicAdd into global scratch.
    float* __restrict__ gs = g_sums + b * KK * DD;
    for (int i = tid; i < KK * DD; i += THREADS1) {
        float s = sacc[0][i] + sacc[1][i] + sacc[2][i] + sacc[3][i];
        atomicAdd(&gs[i], s);
    }
    float* __restrict__ gc = g_cnt + b * KK;
    for (int i = tid; i < KK; i += THREADS1) {
        atomicAdd(&gc[i], scnt[0][i] + scnt[1][i] + scnt[2][i] + scnt[3][i]);
    }
}

// ---------------------------------------------------------------------------
// Kernel 2: per-batch centroid pairwise push loss, mean over batches into out
// ---------------------------------------------------------------------------
#define CSTRIDE (DD + 1)   // pad to kill bank conflicts on j-varying reads

__global__ void finalize_kernel(float* __restrict__ out) {
    const int b   = blockIdx.x;
    const int tid = threadIdx.x;

    __shared__ float cent[KK * CSTRIDE];  // ~8.4 KB
    __shared__ float cnts[KK];
    __shared__ float red[256];

    for (int i = tid; i < KK; i += 256)
        cnts[i] = g_cnt[b * KK + i];
    __syncthreads();

    for (int i = tid; i < KK * DD; i += 256) {
        int k = i >> 5;        // i / 32
        int d = i & 31;
        cent[k * CSTRIDE + d] = g_sums[b * KK * DD + i] / fmaxf(cnts[k], 1.0f);
    }
    __syncthreads();

    float local = 0.0f;
    for (int pr = tid; pr < KK * KK; pr += 256) {
        int i = pr >> 6;       // pr / 64
        int j = pr & 63;
        if (i < j && cnts[i] > 0.5f && cnts[j] > 0.5f) {
            float ds = 0.0f;
#pragma unroll
            for (int d = 0; d < DD; d++)
                ds += fabsf(cent[i * CSTRIDE + d] - cent[j * CSTRIDE + d]);
            float h = fmaxf(PUSH_MARGIN - ds, 0.0f);
            local += h * h;
        }
    }
    red[tid] = local;
    __syncthreads();
    for (int s = 128; s > 0; s >>= 1) {
        if (tid < s) red[tid] += red[tid + s];
        __syncthreads();
    }

    if (tid == 0) {
        float n = 0.0f;
        for (int k = 0; k < KK; k++)
            n += (cnts[k] > 0.5f) ? 1.0f : 0.0f;
        float ncomp = n * (n - 1.0f) * 0.5f;
        float push = red[0] / ncomp;
        atomicAdd(out, push / (float)BB);
    }
}

// ---------------------------------------------------------------------------
// Launch
// ---------------------------------------------------------------------------
extern "C" void kernel_launch(void* const* d_in, const int* in_sizes, int n_in,
                              void* d_out, int out_size) {
    const float* emb = (const float*)d_in[0];
    const int*   lab = (const int*)d_in[1];
    float*       out = (float*)d_out;

    // Zero scratch + output (output buffer is poisoned before timing)
    zero_kernel<<<(BB * KK * DD + 255) / 256, 256>>>(out);

    // Segment reduction
    dim3 grid1(BLOCKS_PER_BATCH, BB);
    seg_reduce_kernel<<<grid1, THREADS1>>>(emb, lab);

    // Pairwise loss + mean
    finalize_kernel<<<BB, 256>>>(out);
}

// round 3
// speedup vs baseline: 1.7012x; 1.7012x over previous
#include <cuda_runtime.h>
#include <cuda_bf16.h>
#include <math.h>

// Problem constants (fixed shapes from setup_inputs)
#define BB 8
#define NN (512*512)      // points per batch
#define DD 32             // embedding dim == warp size
#define KK 64             // instances
#define PUSH_MARGIN 0.25f

// Kernel-1 tiling: 512 blocks total -> single wave at 6 blocks/SM occupancy
#define BLOCKS_PER_BATCH 64
#define THREADS1 128
#define WARPS1 4
#define PPB (NN / BLOCKS_PER_BATCH)   // 4096 points per block
#define PPW (PPB / WARPS1)            // 1024 points per warp
#define GRP 16                         // points per prefetch group

// Scratch (device globals: no allocation allowed)
__device__ float g_sums[BB * KK * DD];
__device__ float g_cnt[BB * KK];

// ---------------------------------------------------------------------------
// Kernel 0: zero scratch + output (output is poisoned before each timing run)
// ---------------------------------------------------------------------------
__global__ void zero_kernel(float* __restrict__ out) {
    int i = blockIdx.x * blockDim.x + threadIdx.x;
    if (i < BB * KK * DD) g_sums[i] = 0.0f;
    if (i < BB * KK)      g_cnt[i]  = 0.0f;
    if (i == 0)           out[0]    = 0.0f;
}

// ---------------------------------------------------------------------------
// Kernel 1: segment sum with explicit double-buffered prefetch.
//
// Each warp owns a private [K][32] accumulator in shared memory (bank == lane,
// conflict-free, no atomics in the accumulate). The A/B register buffers force
// 16 LDGs (2KB) in flight per warp while the previous group is consumed:
// prefetch instructions precede consume instructions in program order, so
// in-order issue guarantees the MLP regardless of ptxas scheduling choices.
// ---------------------------------------------------------------------------
__global__ __launch_bounds__(THREADS1)
void seg_reduce_kernel(const float* __restrict__ emb, const int* __restrict__ lab) {
    __shared__ float sacc[WARPS1][KK * DD];   // 32 KB
    __shared__ float scnt[WARPS1][KK];        // 1 KB

    const int tid  = threadIdx.x;
    const int w    = tid >> 5;
    const int lane = tid & 31;
    const int b    = blockIdx.y;

    for (int i = tid; i < WARPS1 * KK * DD; i += THREADS1)
        ((float*)sacc)[i] = 0.0f;
    for (int i = tid; i < WARPS1 * KK; i += THREADS1)
        ((float*)scnt)[i] = 0.0f;
    __syncthreads();

    const int p0   = blockIdx.x * PPB + w * PPW;
    const int pend = p0 + PPW;
    const float* __restrict__ eb = emb + (size_t)b * NN * DD;
    const int*   __restrict__ lb = lab + (size_t)b * NN;
    float* __restrict__ acc = sacc[w];
    float* __restrict__ cnt = scnt[w];

    float vA[GRP], vB[GRP];
    int   lA, lB;
    const int lsel = lane & (GRP - 1);

    // prime buffer A with group at p0
    {
        const float* base = eb + (size_t)p0 * DD + lane;
        lA = lb[p0 + lsel];
#pragma unroll
        for (int j = 0; j < GRP; j++) vA[j] = base[j * DD];
    }

    // process 2 groups (32 points) per iteration; PPW % 32 == 0
#pragma unroll 1
    for (int p = p0; p < pend; p += 2 * GRP) {
        // ---- prefetch B (p+16): always in range (p <= pend-32) ----
        {
            const float* base = eb + (size_t)(p + GRP) * DD + lane;
            lB = lb[p + GRP + lsel];
#pragma unroll
            for (int j = 0; j < GRP; j++) vB[j] = base[j * DD];
        }
        // ---- consume A ----
        if (lane < GRP) atomicAdd(&cnt[lA], 1.0f);
#pragma unroll
        for (int j = 0; j < GRP; j++) {
            int l = __shfl_sync(0xffffffffu, lA, j);
            acc[l * DD + lane] += vA[j];
        }
        // ---- prefetch A (p+32): guard last iteration ----
        if (p + 2 * GRP < pend) {
            const float* base = eb + (size_t)(p + 2 * GRP) * DD + lane;
            lA = lb[p + 2 * GRP + lsel];
#pragma unroll
            for (int j = 0; j < GRP; j++) vA[j] = base[j * DD];
        }
        // ---- consume B ----
        if (lane < GRP) atomicAdd(&cnt[lB], 1.0f);
#pragma unroll
        for (int j = 0; j < GRP; j++) {
            int l = __shfl_sync(0xffffffffu, lB, j);
            acc[l * DD + lane] += vB[j];
        }
    }
    __syncthreads();

    // Flush: combine the 4 warp accumulators, atomicAdd into global scratch.
    float* __restrict__ gs = g_sums + b * KK * DD;
    for (int i = tid; i < KK * DD; i += THREADS1) {
        float s = sacc[0][i] + sacc[1][i] + sacc[2][i] + sacc[3][i];
        atomicAdd(&gs[i], s);
    }
    float* __restrict__ gc = g_cnt + b * KK;
    for (int i = tid; i < KK; i += THREADS1) {
        atomicAdd(&gc[i], scnt[0][i] + scnt[1][i] + scnt[2][i] + scnt[3][i]);
    }
}

// ---------------------------------------------------------------------------
// Kernel 2: per-batch centroid pairwise push loss, mean over batches into out
// ---------------------------------------------------------------------------
#define CSTRIDE (DD + 1)   // pad to kill bank conflicts on j-varying reads

__global__ void finalize_kernel(float* __restrict__ out) {
    const int b   = blockIdx.x;
    const int tid = threadIdx.x;

    __shared__ float cent[KK * CSTRIDE];  // ~8.4 KB
    __shared__ float cnts[KK];
    __shared__ float red[256];

    for (int i = tid; i < KK; i += 256)
        cnts[i] = g_cnt[b * KK + i];
    __syncthreads();

    for (int i = tid; i < KK * DD; i += 256) {
        int k = i >> 5;        // i / 32
        int d = i & 31;
        cent[k * CSTRIDE + d] = g_sums[b * KK * DD + i] / fmaxf(cnts[k], 1.0f);
    }
    __syncthreads();

    float local = 0.0f;
    for (int pr = tid; pr < KK * KK; pr += 256) {
        int i = pr >> 6;       // pr / 64
        int j = pr & 63;
        if (i < j && cnts[i] > 0.5f && cnts[j] > 0.5f) {
            float ds = 0.0f;
#pragma unroll
            for (int d = 0; d < DD; d++)
                ds += fabsf(cent[i * CSTRIDE + d] - cent[j * CSTRIDE + d]);
            float h = fmaxf(PUSH_MARGIN - ds, 0.0f);
            local += h * h;
        }
    }
    red[tid] = local;
    __syncthreads();
    for (int s = 128; s > 0; s >>= 1) {
        if (tid < s) red[tid] += red[tid + s];
        __syncthreads();
    }

    if (tid == 0) {
        float n = 0.0f;
        for (int k = 0; k < KK; k++)
            n += (cnts[k] > 0.5f) ? 1.0f : 0.0f;
        float ncomp = n * (n - 1.0f) * 0.5f;
        float push = red[0] / ncomp;
        atomicAdd(out, push / (float)BB);
    }
}

// ---------------------------------------------------------------------------
// Launch
// ---------------------------------------------------------------------------
extern "C" void kernel_launch(void* const* d_in, const int* in_sizes, int n_in,
                              void* d_out, int out_size) {
    const float* emb = (const float*)d_in[0];
    const int*   lab = (const int*)d_in[1];
    float*       out = (float*)d_out;

    // Zero scratch + output (output buffer is poisoned before timing)
    zero_kernel<<<(BB * KK * DD + 255) / 256, 256>>>(out);

    // Segment reduction
    dim3 grid1(BLOCKS_PER_BATCH, BB);
    seg_reduce_kernel<<<grid1, THREADS1>>>(emb, lab);

    // Pairwise loss + mean
    finalize_kernel<<<BB, 256>>>(out);
}